// round 10
// baseline (speedup 1.0000x reference)
#include <cuda_runtime.h>
#include <cuda_fp16.h>
#include <cuda_bf16.h>
#include <cstdint>

// Problem constants
#define B_BATCH 64
#define T_LEN   2048
#define F_DIM   256
#define BT      (B_BATCH * T_LEN)   // 131072
#define NSB     (BT / 256)          // 512 super-blocks of 256 rows
#define NCTA    152                 // GB300: 152 SMs, persistent 1 CTA/SM
#define HSTEP   (NCTA / 2)          // 76 CTAs per N-half

// ---------------------------------------------------------------------------
// Scratch (no allocations allowed -> device globals)
// ---------------------------------------------------------------------------
__device__ __half g_Wh[F_DIM * F_DIM];  // W^T in fp16: g_Wh[g*256+f] = W[f][g]
__device__ __half g_xh[(long)BT * F_DIM]; // x in fp16 (written by k_ait h==0)
__device__ float g_aitp[2][BT];         // per-half partial ait
__device__ float g_sum[B_BATCH];
__device__ float g_part[16 * B_BATCH * F_DIM];

__device__ __forceinline__ uint32_t smem_u32(const void* p) {
    uint32_t a;
    asm("{ .reg .u64 t; cvta.to.shared.u64 t, %1; cvt.u32.u64 %0, t; }" : "=r"(a) : "l"(p));
    return a;
}
__device__ __forceinline__ void cp16(uint32_t dst, const void* src) {
    asm volatile("cp.async.cg.shared.global [%0], [%1], 16;" :: "r"(dst), "l"(src));
}
#define CP_COMMIT()  asm volatile("cp.async.commit_group;" ::: "memory")
#define CP_WAIT(n)   asm volatile("cp.async.wait_group %0;" :: "n"(n) : "memory")
#define LDMATRIX_X4(r0, r1, r2, r3, addr) \
    asm volatile("ldmatrix.sync.aligned.m8n8.x4.shared.b16 {%0,%1,%2,%3}, [%4];" \
                 : "=r"(r0), "=r"(r1), "=r"(r2), "=r"(r3) : "r"(addr))

// ---------------------------------------------------------------------------
// Phase 0: W -> fp16, transposed to [g][f] (K-major for the B operand)
// ---------------------------------------------------------------------------
__global__ void __launch_bounds__(256) k_wt(const float* __restrict__ W)
{
    __shared__ float tile[32][33];
    const int tx = threadIdx.x, ty = threadIdx.y;
    const int gx = blockIdx.x * 32, gy = blockIdx.y * 32;
    #pragma unroll
    for (int j = ty; j < 32; j += 8)
        tile[j][tx] = W[(gy + j) * F_DIM + gx + tx];
    __syncthreads();
    #pragma unroll
    for (int j = ty; j < 32; j += 8)
        g_Wh[(gx + j) * F_DIM + gy + tx] = __float2half_rn(tile[tx][j]);
}

// ---------------------------------------------------------------------------
// Phase 1 (persistent, N-split, fp16 mma, ldmatrix fragments)
//   CTA h = blockIdx.x & 1 owns cols [128h, 128h+128).
//   B half (fp16, [n][k], word-stride 132) resident in smem, loaded once.
//   A streamed per super-block (256 rows) in 8 double-buffered k=32 chunks:
//   LDG float4 (one chunk ahead) -> cvt fp16 -> STS (+ STG to g_xh if h==0).
//   8 warps: 4(row) x 2(col) grid of 64x64 tiles; mma.sync m16n8k16 f16.f32.
// ---------------------------------------------------------------------------
#define SA_W 20                 // A row stride, words (20 mod 8 == 4)
#define SB_W 132                // B row stride, words (132 mod 8 == 4)
#define A_BUF_W (256 * SA_W)    // 5120 words
#define OFF_A0 0
#define OFF_A1 A_BUF_W                        // 5120
#define OFF_B  (2 * A_BUF_W)                  // 10240
#define B_WORDS (128 * SB_W)                  // 16896
#define OFF_U  (OFF_B + B_WORDS)              // 27136 (floats)
#define OFF_BI (OFF_U + 128)                  // 27264
#define OFF_SR (OFF_BI + 128)                 // 27392
#define SMEM_WORDS (OFF_SR + 512)             // 27904
#define SMEM_BYTES (SMEM_WORDS * 4)           // 111,616

__global__ void __launch_bounds__(256, 1) k_ait(
    const float* __restrict__ x, const float* __restrict__ bias,
    const float* __restrict__ u)
{
    extern __shared__ uint32_t smw[];
    const uint32_t smb = smem_u32(smw);
    const int tid  = threadIdx.x;
    const int lane = tid & 31;
    const int wid  = tid >> 5;
    const int q    = lane >> 2;          // groupID (row within frag)
    const int m    = lane & 3;           // threadID-in-group
    const int mrow = (wid >> 1) * 64;    // row-group base (0..192)
    const int cg   = wid & 1;            // col-group 0..1
    const int ncol = cg * 64;
    const int h    = blockIdx.x & 1;     // N-half

    // ldmatrix per-lane address components (in words)
    const uint32_t a_lane = (lane & 15) * SA_W + ((lane >> 4) << 2);
    const uint32_t b_lane_n = (lane & 7) + ((lane >> 4) << 3);
    const uint32_t b_lane_k = ((lane >> 3) & 1) << 2;

    float* usp = reinterpret_cast<float*>(smw + OFF_U);
    float* bip = reinterpret_cast<float*>(smw + OFF_BI);
    if (tid < 128) {
        usp[tid] = u[h * 128 + tid];
        bip[tid] = bias[h * 128 + tid];
    }

    // Resident B half via cp.async: g_Wh rows n = 128h..128h+127, 256 halfs.
    {
        #pragma unroll
        for (int i = 0; i < 16; i++) {           // 4096 x 16B
            int idx = i * 256 + tid;
            int n = idx >> 5, c16 = idx & 31;    // 32 x 16B per row
            cp16(smb + (OFF_B + n * SB_W + c16 * 4) * 4,
                 g_Wh + (h * 128 + n) * F_DIM + c16 * 8);
        }
        CP_COMMIT();
    }

    const float4* xg4 = reinterpret_cast<const float4*>(x);
    uint2* gx2 = reinterpret_cast<uint2*>(g_xh);

    // LDG chunk c (k = 32c..32c+31) of super-block sb into registers.
    auto ldgA = [&](int sb_, int c_, float4* R) {
        const float4* xg = xg4 + (long)sb_ * 256 * 64;
        #pragma unroll
        for (int i = 0; i < 8; i++) {
            int idx = i * 256 + tid;
            int r = idx >> 3, c4 = idx & 7;      // 8 float4 per 32-k row
            R[i] = __ldg(xg + r * 64 + c_ * 8 + c4);
        }
    };
    // Convert + store registers into A buffer bsel; h==0 CTAs also persist
    // the fp16 x to g_xh for k_wsum.
    auto stsA = [&](const float4* R, int bsel, int sb_, int c_) {
        uint32_t* ab = smw + (bsel ? OFF_A1 : OFF_A0);
        #pragma unroll
        for (int i = 0; i < 8; i++) {
            int idx = i * 256 + tid;
            int r = idx >> 3, c4 = idx & 7;
            __half2 h0 = __floats2half2_rn(R[i].x, R[i].y);
            __half2 h1 = __floats2half2_rn(R[i].z, R[i].w);
            uint2 v;
            v.x = *reinterpret_cast<uint32_t*>(&h0);
            v.y = *reinterpret_cast<uint32_t*>(&h1);
            *reinterpret_cast<uint2*>(ab + r * SA_W + c4 * 2) = v;
            if (h == 0)
                gx2[((long)sb_ * 256 + r) * 64 + c_ * 8 + c4] = v;
        }
    };

    int sb = blockIdx.x >> 1;
    float4 R[8];
    ldgA(sb, 0, R);
    CP_WAIT(0);                  // B resident ready

    for (; sb < NSB; sb += HSTEP) {
        stsA(R, 0, sb, 0);
        __syncthreads();
        ldgA(sb, 1, R);

        float acc[4][8][4];
        #pragma unroll
        for (int mt = 0; mt < 4; mt++)
            #pragma unroll
            for (int nt = 0; nt < 8; nt++)
                #pragma unroll
                for (int i = 0; i < 4; i++) acc[mt][nt][i] = 0.f;

        for (int c = 0; c < 8; c++) {
            const uint32_t abase = (c & 1) ? OFF_A1 : OFF_A0;

            #pragma unroll
            for (int s = 0; s < 2; s++) {        // two k16 steps per chunk
                const int kb = 8 * s;            // word offset within chunk
                uint32_t a[4][4];
                #pragma unroll
                for (int mt = 0; mt < 4; mt++)
                    LDMATRIX_X4(a[mt][0], a[mt][1], a[mt][2], a[mt][3],
                        smb + (abase + (mrow + mt * 16) * SA_W + kb + a_lane) * 4);
                uint32_t b0[8], b1[8];
                #pragma unroll
                for (int p = 0; p < 4; p++)
                    LDMATRIX_X4(b0[2 * p], b1[2 * p], b0[2 * p + 1], b1[2 * p + 1],
                        smb + (OFF_B + (ncol + p * 16 + b_lane_n) * SB_W
                               + c * 16 + kb + b_lane_k) * 4);
                #pragma unroll
                for (int mt = 0; mt < 4; mt++)
                    #pragma unroll
                    for (int nt = 0; nt < 8; nt++) {
                        asm volatile(
                            "mma.sync.aligned.m16n8k16.row.col.f32.f16.f16.f32 "
                            "{%0,%1,%2,%3}, {%4,%5,%6,%7}, {%8,%9}, {%0,%1,%2,%3};"
                            : "+f"(acc[mt][nt][0]), "+f"(acc[mt][nt][1]),
                              "+f"(acc[mt][nt][2]), "+f"(acc[mt][nt][3])
                            : "r"(a[mt][0]), "r"(a[mt][1]),
                              "r"(a[mt][2]), "r"(a[mt][3]),
                              "r"(b0[nt]), "r"(b1[nt]));
                    }
            }

            __syncthreads();
            if (c < 7) {
                stsA(R, (c + 1) & 1, sb, c + 1);  // chunk c+1 into its buffer
                int nsb2 = sb, nc = c + 2;        // prefetch chunk c+2 (or next sb's 0)
                if (nc > 7) { nsb2 = min(sb + HSTEP, NSB - 1); nc = 0; }
                ldgA(nsb2, nc, R);
                __syncthreads();
            }
        }
        // R now holds chunk 0 of the next super-block (LDG issued at c==6).

        // Epilogue: tanh(acc + bias)*u via MUFU, per-row partial over 128 cols.
        float* sred = reinterpret_cast<float*>(smw + OFF_SR);   // [256][2]
        #pragma unroll
        for (int mt = 0; mt < 4; mt++) {
            float sA = 0.f, sB = 0.f;
            #pragma unroll
            for (int nt = 0; nt < 8; nt++) {
                const int col = ncol + nt * 8 + 2 * m;
                #pragma unroll
                for (int hh = 0; hh < 2; hh++) {
                    float z0 = acc[mt][nt][hh]     + bip[col + hh];
                    float z1 = acc[mt][nt][hh + 2] + bip[col + hh];
                    z0 = fminf(fmaxf(z0, -15.f), 15.f);
                    z1 = fminf(fmaxf(z1, -15.f), 15.f);
                    const float e0 = __expf(2.f * z0);
                    const float e1 = __expf(2.f * z1);
                    sA = fmaf(__fdividef(e0 - 1.f, e0 + 1.f), usp[col + hh], sA);
                    sB = fmaf(__fdividef(e1 - 1.f, e1 + 1.f), usp[col + hh], sB);
                }
            }
            sA += __shfl_xor_sync(0xffffffffu, sA, 1);
            sA += __shfl_xor_sync(0xffffffffu, sA, 2);
            sB += __shfl_xor_sync(0xffffffffu, sB, 1);
            sB += __shfl_xor_sync(0xffffffffu, sB, 2);
            if (m == 0) {
                const int r = mrow + mt * 16 + q;
                sred[r * 2 + cg]       = sA;
                sred[(r + 8) * 2 + cg] = sB;
            }
        }
        __syncthreads();
        g_aitp[h][(long)sb * 256 + tid] = sred[tid * 2] + sred[tid * 2 + 1];
        __syncthreads();   // sred reads done before next block's epilogue writes
    }
}

// ---------------------------------------------------------------------------
// Phase 2: g_sum[b] = sum_t exp(ait[b,t]),  ait = p0 + p1
// ---------------------------------------------------------------------------
__global__ void __launch_bounds__(256) k_softsum()
{
    __shared__ float red[256];
    const int b = blockIdx.x, tid = threadIdx.x;
    float s = 0.f;
    for (int i = tid; i < T_LEN; i += 256) {
        const int r = b * T_LEN + i;
        s += expf(g_aitp[0][r] + g_aitp[1][r]);
    }
    red[tid] = s;
    __syncthreads();
    for (int off = 128; off > 0; off >>= 1) {
        if (tid < off) red[tid] += red[tid + off];
        __syncthreads();
    }
    if (tid == 0) g_sum[b] = red[0];
}

// ---------------------------------------------------------------------------
// Phase 3: partial weighted sums over 128-t chunks, reading fp16 x (g_xh).
// Deterministic: each (b,t) weight computed in exactly one CTA.
// ---------------------------------------------------------------------------
__global__ void __launch_bounds__(256) k_wsum()
{
    __shared__ float as[128];
    __shared__ float sp[8 * 256];
    const int chunk = blockIdx.x, b = blockIdx.y, tid = threadIdx.x;
    const int t0 = chunk * 128;
    const float inv = 1.f / (g_sum[b] + 1e-7f);
    if (tid < 128) {
        const int r = b * T_LEN + t0 + tid;
        as[tid] = expf(g_aitp[0][r] + g_aitp[1][r]) * inv;
    }
    __syncthreads();

    const int f8 = tid & 31, ts = tid >> 5;   // f8: 8-half group, ts: t-slice
    const uint4* xb = reinterpret_cast<const uint4*>(
        g_xh + ((long)(b * T_LEN + t0)) * F_DIM);
    float r8[8];
    #pragma unroll
    for (int j = 0; j < 8; j++) r8[j] = 0.f;
    #pragma unroll 4
    for (int tt = ts; tt < 128; tt += 8) {
        const uint4 v = xb[tt * 32 + f8];
        const float a = as[tt];
        const float2 f0 = __half22float2(*reinterpret_cast<const __half2*>(&v.x));
        const float2 f1 = __half22float2(*reinterpret_cast<const __half2*>(&v.y));
        const float2 f2 = __half22float2(*reinterpret_cast<const __half2*>(&v.z));
        const float2 f3 = __half22float2(*reinterpret_cast<const __half2*>(&v.w));
        r8[0] = fmaf(f0.x, a, r8[0]); r8[1] = fmaf(f0.y, a, r8[1]);
        r8[2] = fmaf(f1.x, a, r8[2]); r8[3] = fmaf(f1.y, a, r8[3]);
        r8[4] = fmaf(f2.x, a, r8[4]); r8[5] = fmaf(f2.y, a, r8[5]);
        r8[6] = fmaf(f3.x, a, r8[6]); r8[7] = fmaf(f3.y, a, r8[7]);
    }
    #pragma unroll
    for (int j = 0; j < 8; j++)
        sp[ts * 256 + f8 * 8 + j] = r8[j];
    __syncthreads();
    float s = 0.f;
    #pragma unroll
    for (int t2 = 0; t2 < 8; t2++)
        s += sp[t2 * 256 + tid];
    g_part[(chunk * B_BATCH + b) * F_DIM + tid] = s;
}

// ---------------------------------------------------------------------------
// Phase 4: reduce 16 partials -> out[b,f] (float4)
// ---------------------------------------------------------------------------
__global__ void __launch_bounds__(64) k_red(float* __restrict__ out)
{
    const int b = blockIdx.x, tid = threadIdx.x;
    const float4* gp = reinterpret_cast<const float4*>(g_part);
    float4 s = make_float4(0.f, 0.f, 0.f, 0.f);
    #pragma unroll
    for (int c = 0; c < 16; c++) {
        const float4 v = gp[(c * B_BATCH + b) * 64 + tid];
        s.x += v.x; s.y += v.y; s.z += v.z; s.w += v.w;
    }
    reinterpret_cast<float4*>(out)[b * 64 + tid] = s;
}

// ---------------------------------------------------------------------------
extern "C" void kernel_launch(void* const* d_in, const int* in_sizes, int n_in,
                              void* d_out, int out_size)
{
    const float* x    = (const float*)d_in[0];
    const float* W    = (const float*)d_in[1];
    const float* bias = (const float*)d_in[2];
    const float* u    = (const float*)d_in[3];
    float* out = (float*)d_out;

    cudaFuncSetAttribute(k_ait, cudaFuncAttributeMaxDynamicSharedMemorySize, SMEM_BYTES);

    k_wt<<<dim3(8, 8), dim3(32, 8)>>>(W);
    k_ait<<<NCTA, 256, SMEM_BYTES>>>(x, bias, u);   // persistent, N-split halves
    k_softsum<<<B_BATCH, 256>>>();
    k_wsum<<<dim3(16, B_BATCH), 256>>>();
    k_red<<<B_BATCH, 64>>>(out);
}